// round 11
// baseline (speedup 1.0000x reference)
#include <cuda_runtime.h>
#include <math.h>

#define NG   5000
#define IMH  512
#define IMW  512
#define HW   (IMH * IMW)
#define TPB  1024
#define ALPHA_T (1.0f / 255.0f)

// Interleaved RGBA accumulation scratch (16B/pixel -> one v4 red per splat).
// Zero-initialized at module load; phase 2 re-zeroes every call, so
// "scratch == 0 on entry" is an invariant of kernel_launch.
__device__ float4 g_scratch4[HW];

// Sense-reversing grid barrier state (re-entrant across graph replays).
__device__ unsigned          g_cnt   = 0;
__device__ volatile unsigned g_sense = 0;

__device__ __forceinline__ void grid_barrier(int nblk) {
    __syncthreads();
    if (threadIdx.x == 0) {
        const unsigned my = g_sense;
        __threadfence();                       // publish this block's REDs
        const unsigned old = atomicAdd(&g_cnt, 1u);
        if (old == (unsigned)nblk - 1u) {
            g_cnt = 0;
            atomicExch((unsigned*)&g_sense, my + 1u);   // release
        } else {
            unsigned ns = 32;
            while (g_sense == my) { __nanosleep(ns); if (ns < 256) ns += ns; }
        }
    }
    __syncthreads();
}

// fast tanh via __expf: tanh(x) = sgn(x) * (1 - 2/(1 + e^{2|x|}))
__device__ __forceinline__ float fast_tanh(float x) {
    const float ax = fabsf(x);
    const float e  = __expf(2.0f * ax);
    const float t  = 1.0f - 2.0f / (1.0f + e);
    return copysignf(t, x);
}

// sqrt upper bound: x*rsqrt(x) with a pad so the bbox stays a superset
__device__ __forceinline__ float sqrt_ub(float x) {
    return (x > 0.0f) ? x * rsqrtf(x) * 1.0002f : 0.0f;
}

__device__ __forceinline__ void red_add_v4(float4* addr, float r, float g,
                                           float b) {
    asm volatile("red.global.add.v4.f32 [%0], {%1, %2, %3, %4};"
                 :: "l"(addr), "f"(r), "f"(g), "f"(b), "f"(0.0f)
                 : "memory");
}

__global__ void __launch_bounds__(TPB, 2)      // 2 blocks/SM co-resident
fused_kernel(const float* __restrict__ xyz,
             const float* __restrict__ scaling,
             const float* __restrict__ rot,
             const float* __restrict__ feat,
             const float* __restrict__ opac,
             float* __restrict__ out,
             int nblk) {
    const int lane  = threadIdx.x & 31;
    const int wslot = threadIdx.x >> 5;                // 0..31
    const int nwarp = nblk * (TPB / 32);

    // ------------- phase 1: splat gaussians into g_scratch4 ------------------
    // Interleaved mapping: busy warps spread evenly across ALL blocks/SMs.
    for (int g = blockIdx.x + wslot * nblk; g < NG; g += nwarp) {
        const float2 xy = __ldg((const float2*)xyz + g);
        const float2 sc = __ldg((const float2*)scaling + g);
        const float  rt = __ldg(&rot[g]);
        const float  op = __ldg(&opac[g]);
        const float  cr = __ldg(&feat[3 * g + 0]);
        const float  cg = __ldg(&feat[3 * g + 1]);
        const float  cb = __ldg(&feat[3 * g + 2]);

        const float mx = fast_tanh(xy.x);
        const float my = fast_tanh(xy.y);
        const float sx = fabsf(sc.x + 0.5f);
        const float sy = fabsf(sc.y + 0.5f);
        const float theta = (1.0f / (1.0f + __expf(-rt))) * 6.283185307179586f;

        const float cx = 0.5f * ((mx + 1.0f) * (float)IMW - 1.0f);
        const float cy = 0.5f * ((my + 1.0f) * (float)IMH - 1.0f);

        const float sth = __sinf(theta);
        const float cth = __cosf(theta);
        const float sx2 = sx * sx;
        const float sy2 = sy * sy;
        const float a = cth * cth * sx2 + sth * sth * sy2;   // Sigma_xx
        const float b = cth * sth * (sx2 - sy2);             // Sigma_xy
        const float c = sth * sth * sx2 + cth * cth * sy2;   // Sigma_yy
        const float det = a * c - b * b;
        if (!(det > 0.0f)) continue;
        const float inv_det = __fdividef(1.0f, fmaxf(det, 1e-12f));
        const float A =  c * inv_det;
        const float B = -b * inv_det;
        const float C =  a * inv_det;

        if (!(op > ALPHA_T)) continue;
        const float smax = __logf(255.0f * op);  // alpha>1/255 <=> sigma<smax
        if (!(smax > 0.0f)) continue;

        // AABB (superset) of the iso-ellipse sigma == smax
        const float dxm = sqrt_ub(2.0f * smax * a);
        const float dym = sqrt_ub(2.0f * smax * c);

        const int x0 = max(0,       (int)ceilf (cx - dxm));
        const int x1 = min(IMW - 1, (int)floorf(cx + dxm));
        const int y0 = max(0,       (int)ceilf (cy - dym));
        const int y1 = min(IMH - 1, (int)floorf(cy + dym));
        if (x0 > x1 || y0 > y1) continue;

        // pow2-rounded width -> mask/shift pixel indexing (no div/mod)
        const int w  = x1 - x0 + 1;
        const int sh = (w <= 1) ? 0 : (32 - __clz(w - 1));
        const int mask  = (1 << sh) - 1;
        const int total = (y1 - y0 + 1) << sh;

        for (int i = lane; i < total; i += 32) {
            const int px = x0 + (i & mask);
            if (px > x1) continue;                      // pow2 padding reject
            const int py = y0 + (i >> sh);
            const float dx = cx - (float)px;
            const float dy = cy - (float)py;
            const float sigma = 0.5f * (A * dx * dx + C * dy * dy)
                                + B * dx * dy;
            if (sigma >= 0.0f && sigma < smax) {        // == alpha > 1/255
                const float alpha = op * __expf(-sigma);
                red_add_v4(&g_scratch4[py * IMW + px],
                           alpha * cr, alpha * cg, alpha * cb);
            }
        }
    }

    grid_barrier(nblk);

    // ---- phase 2: gather RGBA -> planar out, re-zero scratch (4 px/thread) --
    const int gid = blockIdx.x * TPB + threadIdx.x;    // group of 4 pixels
    if (gid < HW / 4) {
        const float4* s = &g_scratch4[gid * 4];
        float4 s0 = __ldcg(s + 0);
        float4 s1 = __ldcg(s + 1);
        float4 s2 = __ldcg(s + 2);
        float4 s3 = __ldcg(s + 3);

        float4 r4 = make_float4(fminf(fmaxf(s0.x, 0.f), 1.f),
                                fminf(fmaxf(s1.x, 0.f), 1.f),
                                fminf(fmaxf(s2.x, 0.f), 1.f),
                                fminf(fmaxf(s3.x, 0.f), 1.f));
        float4 g4 = make_float4(fminf(fmaxf(s0.y, 0.f), 1.f),
                                fminf(fmaxf(s1.y, 0.f), 1.f),
                                fminf(fmaxf(s2.y, 0.f), 1.f),
                                fminf(fmaxf(s3.y, 0.f), 1.f));
        float4 b4 = make_float4(fminf(fmaxf(s0.z, 0.f), 1.f),
                                fminf(fmaxf(s1.z, 0.f), 1.f),
                                fminf(fmaxf(s2.z, 0.f), 1.f),
                                fminf(fmaxf(s3.z, 0.f), 1.f));

        __stcg((float4*)(out)           + gid, r4);
        __stcg((float4*)(out + HW)      + gid, g4);
        __stcg((float4*)(out + 2 * HW)  + gid, b4);

        const float4 z = make_float4(0.f, 0.f, 0.f, 0.f);
        float4* sw = (float4*)s;
        __stcg(sw + 0, z);
        __stcg(sw + 1, z);
        __stcg(sw + 2, z);
        __stcg(sw + 3, z);                              // restore zero invariant
    }
}

// ---------------------------------------------------------------------------
// Inputs (metadata order): _xyz(N,2) _scaling(N,2) _rotation(N,1)
//                          _features_dc(N,3) _opacity(N,1)
// Output: float32 (1,3,512,512)
// ---------------------------------------------------------------------------
extern "C" void kernel_launch(void* const* d_in, const int* in_sizes, int n_in,
                              void* d_out, int out_size) {
    const float* xyz     = (const float*)d_in[0];
    const float* scaling = (const float*)d_in[1];
    const float* rot     = (const float*)d_in[2];
    const float* feat    = (const float*)d_in[3];
    const float* opac    = (const float*)d_in[4];
    float* out = (float*)d_out;

    int dev = 0, sms = 152;
    cudaGetDevice(&dev);
    cudaDeviceGetAttribute(&sms, cudaDevAttrMultiProcessorCount, dev);
    const int nblk = sms * 2;                      // all co-resident, one wave

    fused_kernel<<<nblk, TPB>>>(xyz, scaling, rot, feat, opac, out, nblk);
}

// round 14
// speedup vs baseline: 1.0226x; 1.0226x over previous
#include <cuda_runtime.h>
#include <math.h>

#define NG   5000
#define IMH  512
#define IMW  512
#define HW   (IMH * IMW)
#define TPB  544                 // 17 warps/block  (R9 geometry: best measured)
#define WPB  (TPB / 32)
#define ALPHA_T (1.0f / 255.0f)

// Interleaved RGBA accumulation scratch (16B/pixel -> one v4 red per splat).
// Zero-initialized at module load; phase 2 re-zeroes every call, so
// "scratch == 0 on entry" is an invariant of kernel_launch.
__device__ float4 g_scratch4[HW];

// Sense-reversing grid barrier state (re-entrant across graph replays).
__device__ unsigned          g_cnt   = 0;
__device__ volatile unsigned g_sense = 0;

__device__ __forceinline__ void grid_barrier(int nblk) {
    __syncthreads();
    if (threadIdx.x == 0) {
        const unsigned my = g_sense;
        __threadfence();                       // publish this block's REDs
        const unsigned old = atomicAdd(&g_cnt, 1u);
        if (old == (unsigned)nblk - 1u) {
            g_cnt = 0;
            atomicExch((unsigned*)&g_sense, my + 1u);   // release
        } else {
            unsigned ns = 32;
            while (g_sense == my) { __nanosleep(ns); if (ns < 256) ns += ns; }
        }
    }
    __syncthreads();
}

// fast tanh via __expf: tanh(x) = sgn(x) * (1 - 2/(1 + e^{2|x|}))
__device__ __forceinline__ float fast_tanh(float x) {
    const float ax = fabsf(x);
    const float e  = __expf(2.0f * ax);
    const float t  = 1.0f - 2.0f / (1.0f + e);
    return copysignf(t, x);
}

// sqrt upper bound: x*rsqrt(x) with a pad so the bbox stays a superset
__device__ __forceinline__ float sqrt_ub(float x) {
    return (x > 0.0f) ? x * rsqrtf(x) * 1.0002f : 0.0f;
}

__device__ __forceinline__ void red_add_v4(float4* addr, float r, float g,
                                           float b) {
    asm volatile("red.global.add.v4.f32 [%0], {%1, %2, %3, %4};"
                 :: "l"(addr), "f"(r), "f"(g), "f"(b), "f"(0.0f)
                 : "memory");
}

__global__ void __launch_bounds__(TPB, 2)      // 2 blocks/SM co-resident
fused_kernel(const float* __restrict__ xyz,
             const float* __restrict__ scaling,
             const float* __restrict__ rot,
             const float* __restrict__ feat,
             const float* __restrict__ opac,
             float* __restrict__ out,
             int nblk) {
    const int lane  = threadIdx.x & 31;
    const int warp  = blockIdx.x * WPB + (threadIdx.x >> 5);   // block-major (R9)
    const int nwarp = nblk * WPB;

    // ------------- phase 1: splat gaussians into g_scratch4 ------------------
    for (int g = warp; g < NG; g += nwarp) {
        const float2 xy = __ldg((const float2*)xyz + g);
        const float2 sc = __ldg((const float2*)scaling + g);
        const float  rt = __ldg(&rot[g]);
        const float  op = __ldg(&opac[g]);

        const float mx = fast_tanh(xy.x);
        const float my = fast_tanh(xy.y);
        const float sx = fabsf(sc.x + 0.5f);
        const float sy = fabsf(sc.y + 0.5f);
        const float theta = (1.0f / (1.0f + __expf(-rt))) * 6.283185307179586f;

        const float cx = 0.5f * ((mx + 1.0f) * (float)IMW - 1.0f);
        const float cy = 0.5f * ((my + 1.0f) * (float)IMH - 1.0f);

        const float sth = __sinf(theta);
        const float cth = __cosf(theta);
        const float sx2 = sx * sx;
        const float sy2 = sy * sy;
        const float a = cth * cth * sx2 + sth * sth * sy2;   // Sigma_xx
        const float b = cth * sth * (sx2 - sy2);             // Sigma_xy
        const float c = sth * sth * sx2 + cth * cth * sy2;   // Sigma_yy
        const float det = a * c - b * b;
        if (!(det > 0.0f)) continue;
        const float inv_det = __fdividef(1.0f, fmaxf(det, 1e-12f));
        const float A =  c * inv_det;
        const float B = -b * inv_det;
        const float C =  a * inv_det;

        if (!(op > ALPHA_T)) continue;
        const float smax = __logf(255.0f * op);  // alpha>1/255 <=> sigma<smax
        if (!(smax > 0.0f)) continue;

        // AABB (superset) of the iso-ellipse sigma == smax
        const float dxm = sqrt_ub(2.0f * smax * a);
        const float dym = sqrt_ub(2.0f * smax * c);

        const int x0 = max(0,       (int)ceilf (cx - dxm));
        const int x1 = min(IMW - 1, (int)floorf(cx + dxm));
        const int y0 = max(0,       (int)ceilf (cy - dym));
        const int y1 = min(IMH - 1, (int)floorf(cy + dym));
        if (x0 > x1 || y0 > y1) continue;

        // pow2-rounded width -> mask/shift pixel indexing (no div/mod)
        const int w  = x1 - x0 + 1;
        const int sh = (w <= 1) ? 0 : (32 - __clz(w - 1));
        const int mask  = (1 << sh) - 1;
        const int total = (y1 - y0 + 1) << sh;

        const float cr = __ldg(&feat[3 * g + 0]);   // load late (after outs)
        const float cg = __ldg(&feat[3 * g + 1]);
        const float cb = __ldg(&feat[3 * g + 2]);

        for (int i = lane; i < total; i += 32) {
            const int px = x0 + (i & mask);
            if (px > x1) continue;                      // pow2 padding reject
            const int py = y0 + (i >> sh);
            const float dx = cx - (float)px;
            const float dy = cy - (float)py;
            const float sigma = 0.5f * (A * dx * dx + C * dy * dy)
                                + B * dx * dy;
            if (sigma >= 0.0f && sigma < smax) {        // == alpha > 1/255
                const float alpha = op * __expf(-sigma);
                red_add_v4(&g_scratch4[py * IMW + px],
                           alpha * cr, alpha * cg, alpha * cb);
            }
        }
    }

    grid_barrier(nblk);

    // ---- phase 2: gather RGBA -> planar out, re-zero scratch (4 px/thread) --
    const int gid = blockIdx.x * TPB + threadIdx.x;    // group of 4 pixels
    if (gid < HW / 4) {
        const float4* s = &g_scratch4[gid * 4];
        float4 s0 = __ldcg(s + 0);
        float4 s1 = __ldcg(s + 1);
        float4 s2 = __ldcg(s + 2);
        float4 s3 = __ldcg(s + 3);

        float4 r4 = make_float4(fminf(fmaxf(s0.x, 0.f), 1.f),
                                fminf(fmaxf(s1.x, 0.f), 1.f),
                                fminf(fmaxf(s2.x, 0.f), 1.f),
                                fminf(fmaxf(s3.x, 0.f), 1.f));
        float4 g4 = make_float4(fminf(fmaxf(s0.y, 0.f), 1.f),
                                fminf(fmaxf(s1.y, 0.f), 1.f),
                                fminf(fmaxf(s2.y, 0.f), 1.f),
                                fminf(fmaxf(s3.y, 0.f), 1.f));
        float4 b4 = make_float4(fminf(fmaxf(s0.z, 0.f), 1.f),
                                fminf(fmaxf(s1.z, 0.f), 1.f),
                                fminf(fmaxf(s2.z, 0.f), 1.f),
                                fminf(fmaxf(s3.z, 0.f), 1.f));

        __stcg((float4*)(out)           + gid, r4);
        __stcg((float4*)(out + HW)      + gid, g4);
        __stcg((float4*)(out + 2 * HW)  + gid, b4);

        const float4 z = make_float4(0.f, 0.f, 0.f, 0.f);
        float4* sw = (float4*)s;
        __stcg(sw + 0, z);
        __stcg(sw + 1, z);
        __stcg(sw + 2, z);
        __stcg(sw + 3, z);                              // restore zero invariant
    }
}

// ---------------------------------------------------------------------------
// Inputs (metadata order): _xyz(N,2) _scaling(N,2) _rotation(N,1)
//                          _features_dc(N,3) _opacity(N,1)
// Output: float32 (1,3,512,512)
// ---------------------------------------------------------------------------
extern "C" void kernel_launch(void* const* d_in, const int* in_sizes, int n_in,
                              void* d_out, int out_size) {
    const float* xyz     = (const float*)d_in[0];
    const float* scaling = (const float*)d_in[1];
    const float* rot     = (const float*)d_in[2];
    const float* feat    = (const float*)d_in[3];
    const float* opac    = (const float*)d_in[4];
    float* out = (float*)d_out;

    int dev = 0, sms = 152;
    cudaGetDevice(&dev);
    cudaDeviceGetAttribute(&sms, cudaDevAttrMultiProcessorCount, dev);
    const int nblk = sms * 2;                      // all co-resident, one wave

    fused_kernel<<<nblk, TPB>>>(xyz, scaling, rot, feat, opac, out, nblk);
}

// round 16
// speedup vs baseline: 1.1866x; 1.1603x over previous
#include <cuda_runtime.h>
#include <math.h>

#define NG   5000
#define IMH  512
#define IMW  512
#define HW   (IMH * IMW)
#define NG4  (HW / 4)            // 65536 float4-groups of 4 pixels
#define TPB  544                 // 17 warps/block  (R9 geometry: best measured)
#define WPB  (TPB / 32)
#define ALPHA_T (1.0f / 255.0f)

// Interleaved RGBA accumulation scratch (16B/pixel -> one v4 red per splat).
// Zero-initialized at module load; phase 2 re-zeroes every call, so
// "scratch == 0 on entry" is an invariant of kernel_launch.
__device__ float4 g_scratch4[HW];

// Sense-reversing grid barrier state (re-entrant across graph replays).
__device__ unsigned          g_cnt   = 0;
__device__ volatile unsigned g_sense = 0;

__device__ __forceinline__ void grid_barrier(int nblk) {
    __syncthreads();
    if (threadIdx.x == 0) {
        const unsigned my = g_sense;
        __threadfence();                       // publish this block's REDs
        const unsigned old = atomicAdd(&g_cnt, 1u);
        if (old == (unsigned)nblk - 1u) {
            g_cnt = 0;
            atomicExch((unsigned*)&g_sense, my + 1u);   // release
        } else {
            unsigned ns = 32;
            while (g_sense == my) { __nanosleep(ns); if (ns < 128) ns += ns; }
        }
    }
    __syncthreads();
}

// fast tanh via __expf: tanh(x) = sgn(x) * (1 - 2/(1 + e^{2|x|}))
__device__ __forceinline__ float fast_tanh(float x) {
    const float ax = fabsf(x);
    const float e  = __expf(2.0f * ax);
    const float t  = 1.0f - 2.0f / (1.0f + e);
    return copysignf(t, x);
}

__device__ __forceinline__ void red_add_v4(float4* addr, float r, float g,
                                           float b) {
    asm volatile("red.global.add.v4.f32 [%0], {%1, %2, %3, %4};"
                 :: "l"(addr), "f"(r), "f"(g), "f"(b), "f"(0.0f)
                 : "memory");
}

__device__ __forceinline__ float clamp01(float v) {
    return fminf(fmaxf(v, 0.f), 1.f);
}

__global__ void __launch_bounds__(TPB, 2)      // 2 blocks/SM co-resident
fused_kernel(const float* __restrict__ xyz,
             const float* __restrict__ scaling,
             const float* __restrict__ rot,
             const float* __restrict__ feat,
             const float* __restrict__ opac,
             float* __restrict__ out,
             int nblk) {
    const int lane  = threadIdx.x & 31;
    const int warp  = blockIdx.x * WPB + (threadIdx.x >> 5);   // block-major (R9)
    const int nwarp = nblk * WPB;

    // ------------- phase 1: splat gaussians into g_scratch4 ------------------
    // 5168 warps >= 5000 gaussians: one gaussian per warp, one pass.
    for (int g = warp; g < NG; g += nwarp) {
        const float2 xy = __ldg((const float2*)xyz + g);
        const float2 sc = __ldg((const float2*)scaling + g);
        const float  rt = __ldg(&rot[g]);
        const float  op = __ldg(&opac[g]);

        const float mx = fast_tanh(xy.x);
        const float my = fast_tanh(xy.y);
        const float sx = fabsf(sc.x + 0.5f);
        const float sy = fabsf(sc.y + 0.5f);
        const float theta = (1.0f / (1.0f + __expf(-rt))) * 6.283185307179586f;

        const float cx = 0.5f * ((mx + 1.0f) * (float)IMW - 1.0f);
        const float cy = 0.5f * ((my + 1.0f) * (float)IMH - 1.0f);

        const float sth = __sinf(theta);
        const float cth = __cosf(theta);
        const float sx2 = sx * sx;
        const float sy2 = sy * sy;
        const float a = cth * cth * sx2 + sth * sth * sy2;   // Sigma_xx
        const float b = cth * sth * (sx2 - sy2);             // Sigma_xy
        const float c = sth * sth * sx2 + cth * cth * sy2;   // Sigma_yy
        const float det = a * c - b * b;
        if (!(det > 0.0f)) continue;
        const float inv_det = __fdividef(1.0f, fmaxf(det, 1e-12f));
        const float A =  c * inv_det;
        const float B = -b * inv_det;
        const float C =  a * inv_det;

        if (!(op > ALPHA_T)) continue;
        const float smax = __logf(255.0f * op);  // alpha>1/255 <=> sigma<smax
        if (!(smax > 0.0f)) continue;

        // exact AABB of the iso-ellipse sigma == smax
        const float dxm = sqrtf(2.0f * smax * a);
        const float dym = sqrtf(2.0f * smax * c);

        const int x0 = max(0,       __float2int_ru(cx - dxm));
        const int x1 = min(IMW - 1, __float2int_rd(cx + dxm));
        const int y0 = max(0,       __float2int_ru(cy - dym));
        const int y1 = min(IMH - 1, __float2int_rd(cy + dym));
        if (x0 > x1 || y0 > y1) continue;

        // pow2-rounded width -> mask/shift pixel indexing (no div/mod)
        const int w  = x1 - x0 + 1;
        const int sh = (w <= 1) ? 0 : (32 - __clz(w - 1));
        const int mask  = (1 << sh) - 1;
        const int total = (y1 - y0 + 1) << sh;

        const float cr = __ldg(&feat[3 * g + 0]);   // load late (after outs)
        const float cg = __ldg(&feat[3 * g + 1]);
        const float cb = __ldg(&feat[3 * g + 2]);

        for (int i = lane; i < total; i += 32) {
            const int px = x0 + (i & mask);
            if (px > x1) continue;                      // pow2 padding reject
            const int py = y0 + (i >> sh);
            const float dx = cx - (float)px;
            const float dy = cy - (float)py;
            const float sigma = 0.5f * (A * dx * dx + C * dy * dy)
                                + B * dx * dy;
            if (sigma >= 0.0f && sigma < smax) {        // == alpha > 1/255
                const float alpha = op * __expf(-sigma);
                red_add_v4(&g_scratch4[py * IMW + px],
                           alpha * cr, alpha * cg, alpha * cb);
            }
        }
    }

    grid_barrier(nblk);

    // ---- phase 2: gather RGBA -> planar out, re-zero scratch ----------------
    // Per-block contiguous chunk of float4-groups (4 px each): every block/SM
    // participates, accesses stay coalesced, ~2.75 mem-ops per pixel.
    const int per_blk = (NG4 + nblk - 1) / nblk;       // 216 for nblk=304
    const int g0 = blockIdx.x * per_blk;
    const int g1 = min(g0 + per_blk, NG4);
    for (int gid = g0 + threadIdx.x; gid < g1; gid += TPB) {
        const float4* s = &g_scratch4[gid * 4];
        float4 s0 = __ldcg(s + 0);
        float4 s1 = __ldcg(s + 1);
        float4 s2 = __ldcg(s + 2);
        float4 s3 = __ldcg(s + 3);

        float4 r4 = make_float4(clamp01(s0.x), clamp01(s1.x),
                                clamp01(s2.x), clamp01(s3.x));
        float4 g4 = make_float4(clamp01(s0.y), clamp01(s1.y),
                                clamp01(s2.y), clamp01(s3.y));
        float4 b4 = make_float4(clamp01(s0.z), clamp01(s1.z),
                                clamp01(s2.z), clamp01(s3.z));

        __stcg((float4*)(out)          + gid, r4);
        __stcg((float4*)(out + HW)     + gid, g4);
        __stcg((float4*)(out + 2 * HW) + gid, b4);

        const float4 z = make_float4(0.f, 0.f, 0.f, 0.f);
        float4* sw = (float4*)s;
        __stcg(sw + 0, z);
        __stcg(sw + 1, z);
        __stcg(sw + 2, z);
        __stcg(sw + 3, z);                              // restore zero invariant
    }
}

// ---------------------------------------------------------------------------
// Inputs (metadata order): _xyz(N,2) _scaling(N,2) _rotation(N,1)
//                          _features_dc(N,3) _opacity(N,1)
// Output: float32 (1,3,512,512)
// ---------------------------------------------------------------------------
extern "C" void kernel_launch(void* const* d_in, const int* in_sizes, int n_in,
                              void* d_out, int out_size) {
    const float* xyz     = (const float*)d_in[0];
    const float* scaling = (const float*)d_in[1];
    const float* rot     = (const float*)d_in[2];
    const float* feat    = (const float*)d_in[3];
    const float* opac    = (const float*)d_in[4];
    float* out = (float*)d_out;

    int dev = 0, sms = 152;
    cudaGetDevice(&dev);
    cudaDeviceGetAttribute(&sms, cudaDevAttrMultiProcessorCount, dev);
    const int nblk = sms * 2;                      // all co-resident, one wave

    fused_kernel<<<nblk, TPB>>>(xyz, scaling, rot, feat, opac, out, nblk);
}